// round 15
// baseline (speedup 1.0000x reference)
#include <cuda_runtime.h>
#include <cuda_fp16.h>
#include <math.h>
#include <stdint.h>

#define BDIM 4096
#define DDIM 512
#define NBINS 10
#define TM 128             // block tile rows
#define TN 64              // block tile cols
#define GX 64
#define GY 32
#define NCTA (GX * GY)     // 2048 launched (~1056 live)
#define KC 32              // fp16 K-elements per stage (64 B/row)
#define NST (DDIM / KC)    // 16 stages
#define SROWB 80           // padded SMEM row stride (64B data + 16B pad)
#define B_OFF (128 * SROWB)            // B tile after A's 128 rows
#define STAGE_B (192 * SROWB)          // A(128 rows) + B(64 rows) = 15360 B
#define NSTAGE 3
#define DYN_SMEM (NSTAGE * STAGE_B)    // 46080 B

// ---------------------------------------------------------------------------
// device scratch (no allocations allowed)
// ---------------------------------------------------------------------------
__device__ __half g_h[BDIM * DDIM];   // fp16 normalized rows
__device__ int   g_tgt[BDIM];
__device__ float g_cntf[NBINS];
__device__ float g_sum[NBINS];
__device__ int   g_ticket;

// ---------------------------------------------------------------------------
// helpers (base-ISA only: cp.async, ldmatrix, mma.sync — compute_103-safe)
// ---------------------------------------------------------------------------
__device__ __forceinline__ uint32_t smem_to_u32(const void* p) {
    uint32_t a;
    asm("{ .reg .u64 t; cvta.to.shared.u64 t, %1; cvt.u32.u64 %0, t; }"
        : "=r"(a) : "l"(p));
    return a;
}
__device__ __forceinline__ void cp16(uint32_t dst, const void* src) {
    asm volatile("cp.async.cg.shared.global [%0], [%1], 16;" :: "r"(dst), "l"(src));
}
#define CP_COMMIT() asm volatile("cp.async.commit_group;" ::: "memory")
#define CP_WAIT(n)  asm volatile("cp.async.wait_group %0;" :: "n"(n) : "memory")

__device__ __forceinline__ void ldsm_x4(uint32_t* r, uint32_t addr) {
    asm volatile("ldmatrix.sync.aligned.m8n8.x4.shared.b16 {%0,%1,%2,%3}, [%4];"
                 : "=r"(r[0]), "=r"(r[1]), "=r"(r[2]), "=r"(r[3]) : "r"(addr));
}
__device__ __forceinline__ void mma_f16(float* d, const uint32_t* a, const uint32_t* b) {
    asm volatile("mma.sync.aligned.m16n8k16.row.col.f32.f16.f16.f32 "
                 "{%0,%1,%2,%3}, {%4,%5,%6,%7}, {%8,%9}, {%0,%1,%2,%3};"
                 : "+f"(d[0]), "+f"(d[1]), "+f"(d[2]), "+f"(d[3])
                 : "r"(a[0]), "r"(a[1]), "r"(a[2]), "r"(a[3]),
                   "r"(b[0]), "r"(b[1]));
}

// ---------------------------------------------------------------------------
// Kernel 1: blocks 0..4095 normalize rows -> fp16; block 4096 decodes targets
// (sniffs int32 vs int64 storage) and zeros histogram/ticket state.
// ---------------------------------------------------------------------------
__global__ void prep_kernel(const float* __restrict__ x,
                            const int* __restrict__ tgt_words) {
    int blk = blockIdx.x;
    int tid = threadIdx.x;  // 0..127

    if (blk == BDIM) {
        __shared__ int s_any_odd;
        if (tid == 0) s_any_odd = 0;
        __syncthreads();
        int local = 0;
        #pragma unroll
        for (int r = 0; r < 32; r++) {
            int i = tid + r * 128;
            local |= tgt_words[2 * i + 1];   // odd word under int64 hypothesis
        }
        if (local) atomicOr(&s_any_odd, 1);
        __syncthreads();
        bool is32 = (s_any_odd != 0);
        #pragma unroll
        for (int r = 0; r < 32; r++) {
            int i = tid + r * 128;
            g_tgt[i] = is32 ? tgt_words[i] : tgt_words[2 * i];
        }
        if (tid < NBINS) { g_cntf[tid] = 0.0f; g_sum[tid] = 0.0f; }
        if (tid == 0) g_ticket = 0;
        return;
    }

    float4 v = ((const float4*)(x + (size_t)blk * DDIM))[tid];
    float ss = v.x * v.x + v.y * v.y + v.z * v.z + v.w * v.w;
    #pragma unroll
    for (int o = 16; o > 0; o >>= 1) ss += __shfl_down_sync(0xffffffffu, ss, o);
    __shared__ float ws[4];
    if ((tid & 31) == 0) ws[tid >> 5] = ss;
    __syncthreads();
    float tot = ws[0] + ws[1] + ws[2] + ws[3];
    float inv = 1.0f / fmaxf(sqrtf(tot), 1e-12f);

    size_t base = (size_t)blk * DDIM + tid * 4;
    *(__half2*)(g_h + base)     = __half2(__float2half(v.x * inv), __float2half(v.y * inv));
    *(__half2*)(g_h + base + 2) = __half2(__float2half(v.z * inv), __float2half(v.w * inv));
}

// ---------------------------------------------------------------------------
// Kernel 2: 128x64 tiles, 3-stage ring, plain-fp16 Gram + fast-path histogram
// + ticket finalize. 256 threads = 8 warps (4 row-bands x 2 col-bands),
// warp tile 32x32 -> 32 acc regs -> 3 CTAs/SM (24 warps).
// ---------------------------------------------------------------------------
__global__ __launch_bounds__(256, 3) void ghm_mma_kernel(
        const float* __restrict__ acc_sum, float* __restrict__ out) {
    int cx = blockIdx.x;        // col block (64 cols)
    int by = blockIdx.y;        // row block (128 rows)
    bool live = (cx >= 2 * by); // upper-triangular blocks only

    __shared__ int   s_tr[TM], s_tc[TN];
    __shared__ float s_cnt[NBINS], s_sum[NBINS];
    __shared__ int   s_last;
    extern __shared__ __align__(16) char dynsmem[];

    int tid = threadIdx.x, wid = tid >> 5, lid = tid & 31;

    if (live) {
        int rowA = by * TM, colB = cx * TN;
        int warp_m = wid & 3;        // 0..3 -> 32-row band
        int warp_n = wid >> 2;       // 0..1 -> 32-col band

        // per-warp symmetric weight (verified R11/R12)
        float wf;
        if (cx >= 2 * by + 2)      wf = 2.0f;
        else if (cx == 2 * by)     wf = (warp_m < 2) ? 1.0f : 2.0f;
        else                       wf = (warp_m < 2) ? 0.0f : 1.0f;

        if (tid < NBINS) { s_cnt[tid] = 0.0f; s_sum[tid] = 0.0f; }
        if (tid < TM) s_tr[tid] = g_tgt[rowA + tid];
        if (tid < TN) s_tc[tid] = g_tgt[colB + tid];

        uint32_t sb = smem_to_u32(dynsmem);
        uint32_t sbase[NSTAGE] = {sb, sb + STAGE_B, sb + 2 * STAGE_B};

        // cp.async: 3 x 16B chunks per thread per stage
        int r0 = tid >> 2, c0 = tid & 3;             // r0 in [0,64)
        int roff   = r0 * DDIM + c0 * 8;
        int roff64 = roff + 64 * DDIM;
        uint32_t doff0 = (uint32_t)(r0 * SROWB + c0 * 16);
        uint32_t doff1 = (uint32_t)((r0 + 64) * SROWB + c0 * 16);
        uint32_t doffB = (uint32_t)(B_OFF + r0 * SROWB + c0 * 16);

        const __half* pA = g_h + (size_t)rowA * DDIM;
        const __half* pB = g_h + (size_t)colB * DDIM;

        float acc[2][4][4];
        #pragma unroll
        for (int mf = 0; mf < 2; mf++)
            #pragma unroll
            for (int nf = 0; nf < 4; nf++)
                #pragma unroll
                for (int r = 0; r < 4; r++) acc[mf][nf][r] = 0.0f;

        // ldsm lane addressing (stage-relative)
        uint32_t a_off = (uint32_t)((warp_m * 32 + (lid & 15)) * SROWB +
                                    (lid >> 4) * 16);
        // B x4 fused nf-pair: lanes 0-15 -> band 2p, lanes 16-31 -> band 2p+1
        uint32_t b_off = (uint32_t)(B_OFF +
                         (warp_n * 32 + (lid & 7)) * SROWB +
                         ((lid >> 3) & 1) * 16 +
                         (lid >> 4) * (8 * SROWB));

        // prologue: issue stages 0, 1
        #pragma unroll
        for (int s = 0; s < 2; s++) {
            uint32_t base = sbase[s];
            cp16(base + doff0, pA + roff);
            cp16(base + doff1, pA + roff64);
            cp16(base + doffB, pB + roff);
            CP_COMMIT();
            pA += KC; pB += KC;
        }

        int cb = 0, ib = 2;
        for (int s = 0; s < NST; s++) {
            CP_WAIT(1);
            __syncthreads();

            if (s + 2 < NST) {
                uint32_t base = sbase[ib];
                cp16(base + doff0, pA + roff);
                cp16(base + doff1, pA + roff64);
                cp16(base + doffB, pB + roff);
                pA += KC; pB += KC;
            }
            CP_COMMIT();

            uint32_t cur = sbase[cb];
            #pragma unroll
            for (int ks = 0; ks < 2; ks++) {
                uint32_t kcol = (uint32_t)(ks * 32);
                uint32_t bf[2][4];
                #pragma unroll
                for (int p = 0; p < 2; p++)
                    ldsm_x4(bf[p], cur + b_off + (uint32_t)(p * 16 * SROWB) + kcol);
                #pragma unroll
                for (int mf = 0; mf < 2; mf++) {
                    uint32_t ah[4];
                    ldsm_x4(ah, cur + a_off + (uint32_t)(mf * 16 * SROWB) + kcol);
                    #pragma unroll
                    for (int nf = 0; nf < 4; nf++)
                        mma_f16(acc[mf][nf], ah, &bf[nf >> 1][(nf & 1) * 2]);
                }
            }
            cb = (cb == 2) ? 0 : cb + 1;
            ib = (ib == 2) ? 0 : ib + 1;
        }

        // ------- epilogue: fast-path histogram (bins 0/1 in registers) -------
        const float E10 = 1.0f + 1e-6f;
        if (wf > 0.0f) {
            float b0s = 0.0f, b0c = 0.0f, b1s = 0.0f, b1c = 0.0f;
            #pragma unroll
            for (int mf = 0; mf < 2; mf++) {
                int rr = warp_m * 32 + mf * 16 + (lid >> 2);
                int tr0 = s_tr[rr], tr8 = s_tr[rr + 8];
                #pragma unroll
                for (int nf = 0; nf < 4; nf++) {
                    int cc = warp_n * 32 + nf * 8 + (lid & 3) * 2;
                    int tc0 = s_tc[cc], tc1 = s_tc[cc + 1];
                    int rowt[4] = {tr0, tr0, tr8, tr8};
                    int colt[4] = {tc0, tc1, tc0, tc1};
                    #pragma unroll
                    for (int e = 0; e < 4; e++) {
                        float cosv = acc[mf][nf][e];
                        float lab  = (rowt[e] == colt[e]) ? 1.0f : 0.0f;
                        float dv   = lab - cosv;
                        float g    = fabsf(dv);
                        float g2   = dv * dv;
                        if (g < 0.1f)       { b0s += g2; b0c += 1.0f; }
                        else if (g < 0.2f)  { b1s += g2; b1c += 1.0f; }
                        else {
                            int idx = (int)(g * 10.0f);
                            if (idx > 9) idx = (g < E10) ? 9 : 10;
                            if (idx < 10) {
                                atomicAdd(&s_sum[idx], wf * g2);
                                atomicAdd(&s_cnt[idx], wf);
                            }
                        }
                    }
                }
            }
            #pragma unroll
            for (int o = 16; o > 0; o >>= 1) {
                b0s += __shfl_down_sync(0xffffffffu, b0s, o);
                b0c += __shfl_down_sync(0xffffffffu, b0c, o);
                b1s += __shfl_down_sync(0xffffffffu, b1s, o);
                b1c += __shfl_down_sync(0xffffffffu, b1c, o);
            }
            if (lid == 0) {
                atomicAdd(&s_sum[0], wf * b0s);
                atomicAdd(&s_cnt[0], wf * b0c);
                atomicAdd(&s_sum[1], wf * b1s);
                atomicAdd(&s_cnt[1], wf * b1c);
            }
        }
        __syncthreads();
        if (tid < NBINS) {
            atomicAdd(&g_sum[tid], s_sum[tid]);
            atomicAdd(&g_cntf[tid], s_cnt[tid]);
        }
    }

    // ----------------- completion ticket: last CTA finalizes -----------------
    __syncthreads();
    if (tid == 0) {
        __threadfence();
        int done = atomicAdd(&g_ticket, 1);
        s_last = (done == NCTA - 1) ? 1 : 0;
    }
    __syncthreads();
    if (s_last && tid == 0) {
        const float tot = (float)BDIM * (float)BDIM;
        float cts[NBINS], sums[NBINS], vn = 0.0f;
        #pragma unroll
        for (int b = 0; b < NBINS; b++) {
            cts[b]  = atomicAdd(&g_cntf[b], 0.0f);  // L2-coherent read
            sums[b] = atomicAdd(&g_sum[b], 0.0f);
            vn += cts[b];
        }
        float loss = 0.0f;
        #pragma unroll
        for (int b = 0; b < NBINS; b++) {
            float accn = 0.5f * acc_sum[b] + 0.5f * cts[b];  // momentum = 0.5
            float w = tot / (accn + 1e-6f);
            loss += sums[b] * w;
        }
        if (vn > 0.0f) loss /= vn;
        loss /= tot;
        *out = loss;
    }
}

extern "C" void kernel_launch(void* const* d_in, const int* in_sizes, int n_in,
                              void* d_out, int out_size) {
    const float* x       = (const float*)d_in[0];
    const float* acc_sum = (const float*)d_in[1];
    const int*   tgt     = (const int*)d_in[2];   // int32 view; prep sniffs layout
    float*       out     = (float*)d_out;

    cudaFuncSetAttribute(ghm_mma_kernel,
                         cudaFuncAttributeMaxDynamicSharedMemorySize, DYN_SMEM);

    prep_kernel<<<BDIM + 1, 128>>>(x, tgt);
    dim3 grid(GX, GY);
    ghm_mma_kernel<<<grid, 256, DYN_SMEM>>>(acc_sum, out);
}